// round 13
// baseline (speedup 1.0000x reference)
#include <cuda_runtime.h>

// DILATE loss — ONE WARP PER BATCH soft-DTW (zero __syncthreads, duty ~1).
// Warp = batch. 6 sequential 64-row strips; lane l owns rows i0=64s+2l+1, i1=i0+1
// (R10 intra-warp pattern: per step cell A=(i0,jA), B=(i1,jA-1); deps are lane-local
// registers + one shfl of the neighbor row; strip boundary rows via per-warp smem,
// in-place safe, __syncwarp only at strip transitions).
// Forward stores softmin gradient weights float4{wdA,wuA,wdB,wuB} at [s][t][lane]
// (coalesced 512B/warp-step); backward re-reads the same slots in reverse order via
// an 8-deep statically-indexed ring — MUFU-free linear recurrence (R11 scheme).
// Base-2 math. TPB=64, grid=128: 2 warps/SM on separate SMSPs.

#define NB      256
#define NN      336
#define NV      7
#define STRIPS  6
#define TSTEPS  400
#define TPB     64
#define OH      240
#define PSTR    12
#define BUFW    416
#define LOG2E   1.4426950408889634f
#define LN2     0.6931471805599453f
#define BIG2    1.442695e8f
#define PF      8
#define FULLM   0xffffffffu
#define WSTRIDE (STRIPS * TSTEPS * 32)     // float4 slots per batch

__device__ float4   g_W[512 + (size_t)NB * WSTRIDE];   // 512-slot front pad
__device__ double   g_shape_acc;
__device__ double   g_temp_acc;
__device__ unsigned g_done;

static __device__ __forceinline__ float ex2f(float x){float r;asm("ex2.approx.f32 %0,%1;":"=f"(r):"f"(x));return r;}
static __device__ __forceinline__ float lg2f(float x){float r;asm("lg2.approx.f32 %0,%1;":"=f"(r):"f"(x));return r;}
static __device__ __forceinline__ float rcpf(float x){float r;asm("rcp.approx.f32 %0,%1;":"=f"(r):"f"(x));return r;}

extern __shared__ float smem[];

__global__ __launch_bounds__(TPB, 1)
void dilate_kernel(const float* __restrict__ outputs,
                   const float* __restrict__ targets,
                   float* __restrict__ out)
{
    const int l  = threadIdx.x & 31;
    const int ws = threadIdx.x >> 5;
    const int b  = blockIdx.x * 2 + ws;

    // per-warp smem: oE/oO = even/odd packed points [OH][PSTR]; bufA/bufB boundaries
    float* oE   = smem + ws * (2 * OH * PSTR + 2 * BUFW);
    float* oO   = oE + OH * PSTR;
    float* bufA = oO + OH * PSTR;           // fwd: R row; bwd: Pu row
    float* bufB = bufA + BUFW;              // bwd: Pd row

    for (int k = l; k < 2 * OH * PSTR; k += 32) oE[k] = 0.f;
    __syncwarp();

    const float* ob  = outputs + (size_t)b * NN * NV;
    const float* tbp = targets + (size_t)b * NN * NV;

    // pack points: 0-based col j -> (j even) oE[j/2+32], (j odd) oO[(j-1)/2+32]
    for (int j = l; j < NN; j += 32) {
        float p[NV]; float nrm = 0.f;
#pragma unroll
        for (int v = 0; v < NV; v++) { p[v] = ob[j * NV + v]; nrm = fmaf(p[v], p[v], nrm); }
        float* dst = (j & 1) ? (oO + (((j - 1) >> 1) + 32) * PSTR)
                             : (oE + ((j >> 1) + 32) * PSTR);
#pragma unroll
        for (int v = 0; v < NV; v++) dst[v] = p[v];
        dst[7] = nrm * LOG2E;
    }
    // forward boundary = DP row 0: R[0][0]=0, else BIG
    for (int k = l; k < BUFW; k += 32) bufA[k] = (k == 0) ? 0.f : BIG2;
    __syncwarp();

    float4* gw_base = g_W + 512 + (size_t)b * WSTRIDE;
    float shape_reg = 0.f;

    // ================= forward =================
    for (int s = 0; s < STRIPS; s++) {
        const int i0 = 64 * s + 2 * l + 1;
        const bool ok0 = (i0 <= NN), ok1 = (i0 + 1 <= NN);
        const bool seedL = (s == STRIPS - 1) && (l == 7);   // i1 == NN
        float tL0[NV], tL1[NV], tn20 = 0.f, tn21 = 0.f;
        if (ok0) {
            float tnr = 0.f;
#pragma unroll
            for (int v = 0; v < NV; v++) { float tv = tbp[(i0 - 1) * NV + v]; tnr = fmaf(tv, tv, tnr); tL0[v] = 2.f * LOG2E * tv; }
            tn20 = tnr * LOG2E;
        } else {
#pragma unroll
            for (int v = 0; v < NV; v++) tL0[v] = 0.f;
        }
        if (ok1) {
            float tnr = 0.f;
#pragma unroll
            for (int v = 0; v < NV; v++) { float tv = tbp[i0 * NV + v]; tnr = fmaf(tv, tv, tnr); tL1[v] = 2.f * LOG2E * tv; }
            tn21 = tnr * LOG2E;
        } else {
#pragma unroll
            for (int v = 0; v < NV; v++) tL1[v] = 0.f;
        }
        if (s == 1 && l == 0) bufA[0] = BIG2;   // corner zero only valid for strip 0

        float Aprev = BIG2, Aprev2 = BIG2, Bprev = BIG2, upB1 = BIG2, upB2 = BIG2;
        float bndP = BIG2, bndC = BIG2;
        if (l == 0) { bndP = bufA[0]; bndC = bufA[1]; }   // cols jA-1, jA for t=0
        float4 po_a = make_float4(0.f,0.f,0.f,0.f), po_c = make_float4(0.f,0.f,0.f,0.f);
        int jA = 1 - 2 * l;
        float4* gw = gw_base + (size_t)(s * TSTEPS) * 32 + l;
        const float* pE = oE + (32 - l) * PSTR;
        const float* pO = oO + (32 - l) * PSTR;

#define FWD_STEP(PTR) do { \
    bool actA = ok0 && ((unsigned)(jA - 1) < (unsigned)NN); \
    bool actB = ok1 && ((unsigned)(jA - 2) < (unsigned)NN); \
    float4 a = *(const float4*)(PTR); \
    float4 c = *(const float4*)((PTR) + 4); \
    float dA = tn20 + c.w; \
    dA = fmaf(-tL0[0], a.x, dA); dA = fmaf(-tL0[1], a.y, dA); \
    dA = fmaf(-tL0[2], a.z, dA); dA = fmaf(-tL0[3], a.w, dA); \
    dA = fmaf(-tL0[4], c.x, dA); dA = fmaf(-tL0[5], c.y, dA); \
    dA = fmaf(-tL0[6], c.z, dA); \
    float D2A = fmaxf(dA, 0.f); \
    float dB = tn21 + po_c.w; \
    dB = fmaf(-tL1[0], po_a.x, dB); dB = fmaf(-tL1[1], po_a.y, dB); \
    dB = fmaf(-tL1[2], po_a.z, dB); dB = fmaf(-tL1[3], po_a.w, dB); \
    dB = fmaf(-tL1[4], po_c.x, dB); dB = fmaf(-tL1[5], po_c.y, dB); \
    dB = fmaf(-tL1[6], po_c.z, dB); \
    float D2B = fmaxf(dB, 0.f); \
    float ru = upB1, rd = upB2; \
    if (l == 0) { ru = bndC; rd = bndP; bndP = bndC; bndC = bufA[jA + 1]; } \
    float m  = fminf(fminf(rd, ru), Aprev); \
    float ed = ex2f(m - rd), eu = ex2f(m - ru), el = ex2f(m - Aprev); \
    float z  = ed + eu + el; \
    float RnA = D2A + m - lg2f(z); \
    float rz  = rcpf(z); \
    RnA = actA ? RnA : BIG2; \
    float mB  = fminf(fminf(Aprev2, Aprev), Bprev); \
    float edB = ex2f(mB - Aprev2), euB = ex2f(mB - Aprev), elB = ex2f(mB - Bprev); \
    float zB  = edB + euB + elB; \
    float RnB = D2B + mB - lg2f(zB); \
    float rzB = rcpf(zB); \
    RnB = actB ? RnB : BIG2; \
    *gw = make_float4(ed * rz, eu * rz, edB * rzB, euB * rzB); \
    if (actB) { \
        if (l == 31) bufA[jA - 1] = RnB; \
        if (seedL && jA == NN + 1) shape_reg = RnB * LN2; \
    } \
    float sh = __shfl_up_sync(FULLM, RnB, 1); \
    upB2 = upB1; upB1 = sh; \
    Aprev2 = Aprev; Aprev = RnA; Bprev = RnB; \
    po_a = a; po_c = c; \
    jA++; gw += 32; \
} while (0)

        for (int t2 = 0; t2 < TSTEPS; t2 += 2) {
            FWD_STEP(pE); pE += PSTR;
            FWD_STEP(pO); pO += PSTR;
        }
#undef FWD_STEP
        __syncwarp();
    }

    // ================= backward (MUFU-free linear recurrence) =================
    for (int k = l; k < BUFW; k += 32) { bufA[k] = 0.f; bufB[k] = 0.f; }
    __syncwarp();

    float tacc = 0.f;
    for (int s = STRIPS - 1; s >= 0; s--) {
        const int i0 = 64 * s + 2 * l + 1;
        const bool ok0 = (i0 <= NN), ok1 = (i0 + 1 <= NN);
        const bool seedL = (s == STRIPS - 1) && (l == 7);
        float PuBp = 0.f, PlAp = 0.f, PlBp = 0.f, PdBp1 = 0.f, PdBp2 = 0.f, dnPd = 0.f;
        float4 ring[PF];
        const float4* gw = gw_base + (size_t)(s * TSTEPS + TSTEPS - 1) * 32 + l;
#pragma unroll
        for (int q = 0; q < PF; q++) { ring[q] = *gw; gw -= 32; }
        int jA = TSTEPS - 2 * l;              // t = 399
        float dfA = (float)(i0 - jA);
        float puC = 0.f, pdC = 0.f;
        if (l == 31) { puC = bufA[63 + jA]; pdC = bufB[64 + jA]; }
        for (int tb = 0; tb < TSTEPS / PF; tb++) {
#pragma unroll
            for (int kk = 0; kk < PF; kk++) {
                float4 Wv = ring[kk];
                ring[kk] = *gw; gw -= 32;
                bool actA = ok0 && ((unsigned)(jA - 1) < (unsigned)NN);
                bool actB = ok1 && ((unsigned)(jA - 2) < (unsigned)NN);
                float EA = PuBp + PlAp + PdBp2;
                EA = actA ? EA : 0.f;
                float wlA = 1.f - Wv.x - Wv.y;
                float PdA = EA * Wv.x, PuA = EA * Wv.y, PlA = EA * wlA;
                float sPu = __shfl_down_sync(FULLM, PuA, 1);
                float pu_in = (l == 31) ? puC : sPu;
                float pd_in = (l == 31) ? pdC : dnPd;
                if (l == 31) {                 // prefetch next step's boundary cols
                    puC = bufA[62 + jA];
                    pdC = bufB[63 + jA];
                }
                float EB = pu_in + PlBp + pd_in;
                if (seedL && jA == NN + 1) EB = 1.f;
                EB = actB ? EB : 0.f;
                float wlB = 1.f - Wv.z - Wv.w;
                float PdB = EB * Wv.z, PuB = EB * Wv.w, PlB = EB * wlB;
                tacc = fmaf(EA, dfA * dfA, tacc);
                float dfB = dfA + 2.f;
                tacc = fmaf(EB, dfB * dfB, tacc);
                if (actA && l == 0) { bufA[64 + jA] = PuA; bufB[64 + jA] = PdA; }
                dnPd = __shfl_down_sync(FULLM, PdA, 1);
                PuBp = PuB; PlAp = PlA; PlBp = PlB;
                PdBp2 = PdBp1; PdBp1 = PdB;
                jA--; dfA += 1.f;
            }
        }
        __syncwarp();
    }

    // ------- per-warp reduce + global accumulate; last warp finalizes -------
#pragma unroll
    for (int o2 = 16; o2; o2 >>= 1) tacc += __shfl_down_sync(FULLM, tacc, o2);
    float shp = __shfl_sync(FULLM, shape_reg, 7);
    if (l == 0) {
        atomicAdd(&g_temp_acc, (double)tacc);
        atomicAdd(&g_shape_acc, (double)shp);
        __threadfence();
        unsigned old = atomicAdd(&g_done, 1u);
        if (old == NB - 1) {
            __threadfence();
            double shape    = g_shape_acc / (double)NB;
            double temporal = g_temp_acc / ((double)NN * NN * NB * NB);
            out[0] = (float)(0.5 * shape + 0.5 * temporal);
            g_shape_acc = 0.0;
            g_temp_acc  = 0.0;
            __threadfence();
            g_done = 0u;
        }
    }
}

extern "C" void kernel_launch(void* const* d_in, const int* in_sizes, int n_in,
                              void* d_out, int out_size) {
    const float* outputs = (const float*)d_in[0];
    const float* targets = (const float*)d_in[1];
    static int smem_set = 0;
    int smem_bytes = 2 * (2 * OH * PSTR + 2 * BUFW) * (int)sizeof(float);   // 52736 B
    if (!smem_set) {
        cudaFuncSetAttribute(dilate_kernel, cudaFuncAttributeMaxDynamicSharedMemorySize,
                             smem_bytes);
        smem_set = 1;
    }
    dilate_kernel<<<NB / 2, TPB, smem_bytes>>>(outputs, targets, (float*)d_out);
}

// round 16
// speedup vs baseline: 2.0579x; 2.0579x over previous
#include <cuda_runtime.h>

// DILATE loss — band-wavefront soft-DTW, one CTA per batch (grid 256).
// R16 = R11 champion with reduced wavefront skew: 16-step phases, 48-column
// warp skew (was 32/64). Producer->consumer margin stays >= one full phase
// (17 steps fwd/bwd; 16 for the bwd lane-31 prefetch = exactly one phase).
// Span per pass: 48*10+367 = 847 steps (was 1007, -16%).
// Forward stores softmin gradient weights (wd,wu) float2; backward is the
// MUFU-free linear recurrence E = Pu + Pl + Pd (R11 scheme). Base-2 math.

#define NB    256
#define NN    336
#define NV    7
#define ND    673
#define DS    352
#define TPB   352
#define NW    11
#define W2    512
#define PADJ  64
#define PSTR  12
#define NPTS  (NN + 2*PADJ)
#define LOG2E 1.4426950408889634f
#define LN2   0.6931471805599453f
#define BIG2  1.442695e8f
#define PF    16
#define NPH   53            // phases per pass (span 847 / 16)
#define FULLM 0xffffffffu

// weights, diagonal-major; 32 diag front pad + 64 back pad
__device__ float2   g_W[((size_t)NB * ND + 96) * DS];
__device__ double   g_shape_acc;
__device__ double   g_temp_acc;
__device__ unsigned g_done;

static __device__ __forceinline__ float ex2f(float x){float r;asm("ex2.approx.f32 %0,%1;":"=f"(r):"f"(x));return r;}
static __device__ __forceinline__ float lg2f(float x){float r;asm("lg2.approx.f32 %0,%1;":"=f"(r):"f"(x));return r;}
static __device__ __forceinline__ float rcpf(float x){float r;asm("rcp.approx.f32 %0,%1;":"=f"(r):"f"(x));return r;}

extern __shared__ float smem[];

__global__ __launch_bounds__(TPB, 2)
void dilate_kernel(const float* __restrict__ outputs,
                   const float* __restrict__ targets,
                   float* __restrict__ out) {
    const int b   = blockIdx.x;
    const int tid = threadIdx.x;
    const int w   = tid >> 5;
    const int l   = tid & 31;
    const int i   = 32 * w + l + 1;
    const bool row_ok = (i <= NN);

    float* opack = smem;                     // [NPTS][PSTR]: 0-6 dims, 7 = log2e*||o||^2
    float* bnd1  = opack + NPTS * PSTR;      // fwd: R boundary; bwd: Pu   [NW][W2]
    float* bnd2  = bnd1 + NW * W2;           // bwd: Pd
    __shared__ float warpsum[NW];
    __shared__ float shape_s;

    const float* ob = outputs + (size_t)b * NN * NV;
    const float* tb = targets + (size_t)b * NN * NV;

    for (int k = tid; k < NPTS * PSTR; k += TPB) opack[k] = 0.f;
    __syncthreads();
    for (int k = tid; k < NN * NV; k += TPB) {
        int j = k / NV, v = k - j * NV;
        opack[(j + PADJ) * PSTR + v] = ob[k];
    }
    __syncthreads();
    for (int j = tid; j < NN; j += TPB) {
        float s = 0.f;
#pragma unroll
        for (int v = 0; v < NV; v++) { float x = opack[(j + PADJ) * PSTR + v]; s = fmaf(x, x, s); }
        opack[(j + PADJ) * PSTR + 7] = s * LOG2E;
    }
    float tL[NV], tn2 = 0.f;
    if (row_ok) {
        float tnr = 0.f;
#pragma unroll
        for (int v = 0; v < NV; v++) {
            float tv = tb[(i - 1) * NV + v];
            tnr = fmaf(tv, tv, tnr);
            tL[v] = 2.f * LOG2E * tv;
        }
        tn2 = tnr * LOG2E;
    } else {
#pragma unroll
        for (int v = 0; v < NV; v++) tL[v] = 0.f;
    }
    // forward boundary prefill: BIG2 everywhere except R[0][0]=0 (race-free fill)
    for (int k = tid; k < NW * W2; k += TPB) bnd1[k] = (k == PADJ) ? 0.f : BIG2;
    if (tid == 0) shape_s = 0.f;
    __syncthreads();

    float2* gWb = g_W + 32 * (size_t)DS + (size_t)b * ND * DS;
    const bool nn_lane = (i == NN);

    // ================= forward =================
    {
        float Rprev = BIG2, upc = BIG2, upp = BIG2, prevB = BIG2;
        const int off = 48 * w;
        const int pstart = 3 * w, pend = 3 * w + 22;
        const float* bArow = bnd1 + w * W2 + PADJ;
        float* bAnext = bnd1 + (w + 1) * W2 + PADJ;
        for (int p = 0; p < NPH; p++) {
            if (p >= pstart && p <= pend) {
                int s0 = p << 4;
                int j = s0 - off - l + 1;
                if (p == pstart && l == 0) prevB = bArow[0];
                float2* gptr = gWb + (size_t)(s0 - 16 * w + 2) * DS + i;
                const float* oj = opack + (j - 1 + PADJ) * PSTR;
#pragma unroll 8
                for (int k = 0; k < 16; k++) {
                    bool act = row_ok && ((unsigned)(j - 1) < (unsigned)NN);
                    const float4 a = *(const float4*)(oj);
                    const float4 c = *(const float4*)(oj + 4);
                    float acc0 = tn2 + c.w;
                    acc0 = fmaf(-tL[0], a.x, acc0);
                    acc0 = fmaf(-tL[1], a.y, acc0);
                    acc0 = fmaf(-tL[2], a.z, acc0);
                    acc0 = fmaf(-tL[3], a.w, acc0);
                    acc0 = fmaf(-tL[4], c.x, acc0);
                    acc0 = fmaf(-tL[5], c.y, acc0);
                    acc0 = fmaf(-tL[6], c.z, acc0);
                    float D2 = fmaxf(acc0, 0.f);
                    float ru = upc, rd = upp, curB = 0.f;
                    if (l == 0) { curB = bArow[j]; ru = curB; rd = prevB; }
                    float rl = Rprev;
                    float m  = fminf(fminf(rd, ru), rl);
                    float ed = ex2f(m - rd);
                    float eu = ex2f(m - ru);
                    float el = ex2f(m - rl);
                    float z  = ed + eu + el;
                    float Rn = D2 + m - lg2f(z);
                    float rz = rcpf(z);
                    Rn = act ? Rn : BIG2;
                    if (act) {
                        *gptr = make_float2(ed * rz, eu * rz);
                        if (l == 31 && w < NW - 1) bAnext[j] = Rn;
                        if (nn_lane && j == NN) shape_s = Rn * LN2;
                    }
                    float sh = __shfl_up_sync(FULLM, Rn, 1);
                    upp = upc; upc = sh;
                    if (l == 0) prevB = curB;
                    Rprev = Rn;
                    j++; gptr += DS; oj += PSTR;
                }
            }
            __syncthreads();
        }
    }

    // re-init boundaries for backward: products = 0
    for (int k = tid; k < NW * W2; k += TPB) { bnd1[k] = 0.f; bnd2[k] = 0.f; }
    __syncthreads();

    // ================= backward (pure linear recurrence) =================
    float tacc = 0.f;
    {
        float Plp  = 0.f;
        float PuD1 = 0.f, PdD1 = 0.f;
        float PdD2 = 0.f;
        float puC = 0.f, pdC = 0.f;          // lane31 boundary prefetch regs
        float2 ring[PF];
        const int off = 48 * (10 - w);
        const int pstart = 3 * (10 - w), pend = 3 * (10 - w) + 22;
        const float* b1row = bnd1 + w * W2 + PADJ;
        const float* b2row = bnd2 + w * W2 + PADJ;
        float* b1prev = bnd1 + (w - 1) * W2 + PADJ;
        float* b2prev = bnd2 + (w - 1) * W2 + PADJ;
        for (int p = 0; p < NPH; p++) {
            if (p >= pstart && p <= pend) {
                int s0 = p << 4;
                if (p == pstart) {
                    const float2* pr = gWb + (size_t)(848 - 16 * w - s0) * DS + i;
#pragma unroll
                    for (int q = 0; q < PF; q++) { ring[q] = *pr; pr -= DS; }
                    if (l == 31) {           // first col for lane31: j0 = 336
                        puC = b1row[336];
                        pdC = b2row[336];
                    }
                }
                int j = 367 + off - s0 - l;
                float df = (float)(i - j);
                const float2* ppf = gWb + (size_t)(848 - 16 * w - s0 - PF) * DS + i;
#pragma unroll
                for (int kk = 0; kk < PF; kk++) {
                    bool act = row_ok && ((unsigned)(j - 1) < (unsigned)NN);
                    float2 Wv = ring[kk];
                    ring[kk] = *ppf; ppf -= DS;
                    if (l == 31) {
                        PuD1 = puC; PdD1 = pdC;
                        puC = b1row[j - 1];  // prefetch next step's column
                        pdC = b2row[j - 1];
                    }
                    float En = PuD1 + Plp + PdD2;
                    if (nn_lane && j == NN) En = 1.f;
                    En = act ? En : 0.f;
                    float wl = 1.f - Wv.x - Wv.y;
                    float Pd = En * Wv.x;
                    float Pu = En * Wv.y;
                    float Pl = En * wl;
                    tacc = fmaf(En, df * df, tacc);
                    if (act && l == 0 && w > 0) { b1prev[j] = Pu; b2prev[j] = Pd; }
                    float sPu = __shfl_down_sync(FULLM, Pu, 1);
                    float sPd = __shfl_down_sync(FULLM, Pd, 1);
                    PdD2 = PdD1;
                    if (l != 31) { PuD1 = sPu; PdD1 = sPd; }
                    Plp = Pl;
                    j--; df += 1.f;
                }
            }
            __syncthreads();
        }
    }

    // ------- reduce temporal accumulator, finalize in last CTA -------
#pragma unroll
    for (int o2 = 16; o2; o2 >>= 1) tacc += __shfl_down_sync(FULLM, tacc, o2);
    if (l == 0) warpsum[w] = tacc;
    __syncthreads();
    if (tid == 0) {
        float sum = 0.f;
#pragma unroll
        for (int q = 0; q < NW; q++) sum += warpsum[q];
        atomicAdd(&g_temp_acc, (double)sum);
        atomicAdd(&g_shape_acc, (double)shape_s);
        __threadfence();
        unsigned old = atomicAdd(&g_done, 1u);
        if (old == NB - 1) {
            __threadfence();
            double shape    = g_shape_acc / (double)NB;
            double temporal = g_temp_acc / ((double)NN * NN * NB * NB);
            out[0] = (float)(0.5 * shape + 0.5 * temporal);
            g_shape_acc = 0.0;
            g_temp_acc  = 0.0;
            __threadfence();
            g_done = 0u;
        }
    }
}

extern "C" void kernel_launch(void* const* d_in, const int* in_sizes, int n_in,
                              void* d_out, int out_size) {
    const float* outputs = (const float*)d_in[0];
    const float* targets = (const float*)d_in[1];
    static int smem_set = 0;
    int smem_bytes = (NPTS * PSTR + 2 * NW * W2) * sizeof(float);
    if (!smem_set) {
        cudaFuncSetAttribute(dilate_kernel, cudaFuncAttributeMaxDynamicSharedMemorySize,
                             smem_bytes);
        smem_set = 1;
    }
    dilate_kernel<<<NB, TPB, smem_bytes>>>(outputs, targets, (float*)d_out);
}